// round 4
// baseline (speedup 1.0000x reference)
#include <cuda_runtime.h>
#include <math.h>

// ---------------------------------------------------------------------------
// Scratch (__device__ globals; no runtime allocation)
// ---------------------------------------------------------------------------
#define NMAX 65536
__device__ int                 g_count[NMAX];
__device__ unsigned char       g_flag[NMAX];
__device__ __align__(16) float g_nodemid[NMAX * 80];
__device__ unsigned long long  g_key;        // (count<<32) | ~index
__device__ int                 g_cocount;
__device__ int                 g_colist[4096];
__device__ float               g_w3j[675];
__device__ int                 g_bar[4];

#define MEGA_BLOCKS 296

// Path tables: TP2_PATHS = [(0,2),(1,1),(1,3),(2,0),(2,2),(3,1),(3,3)], l3 = 2
__constant__ int c_l1[7]     = {0, 1, 1, 2, 2, 3, 3};
__constant__ int c_l2[7]     = {2, 1, 3, 0, 2, 1, 3};
__constant__ int c_w3off[8]  = {0, 25, 70, 175, 200, 325, 430, 675};
__constant__ int c_midoff[4] = {0, 5, 20, 45};
__constant__ float c_fact[13] = {1.f, 1.f, 2.f, 6.f, 24.f, 120.f, 720.f, 5040.f,
                                 40320.f, 362880.f, 3628800.f, 39916800.f, 479001600.f};

// ---------------------------------------------------------------------------
// Wigner 3j pieces
// ---------------------------------------------------------------------------
__device__ __forceinline__ float su2_cg(int j1, int m1, int j2, int m2, int j3, int m3) {
    if (m1 + m2 != m3) return 0.f;
    int vmin = max(max(-j1 + j2 + m3, -j1 + m1), 0);
    int vmax = min(min(j2 + j3 + m1, j3 - j1 + j2), j3 + m3);
    float C = sqrtf((2.f * j3 + 1.f) * c_fact[j3 + j1 - j2] * c_fact[j3 - j1 + j2] *
                    c_fact[j1 + j2 - j3] * c_fact[j3 + m3] * c_fact[j3 - m3] /
                    (c_fact[j1 + j2 + j3 + 1] * c_fact[j1 - m1] * c_fact[j1 + m1] *
                     c_fact[j2 - m2] * c_fact[j2 + m2]));
    float S = 0.f;
    for (int v = vmin; v <= vmax; v++) {
        float t = c_fact[j2 + j3 + m1 - v] * c_fact[j1 - m1 + v] /
                  (c_fact[v] * c_fact[j3 - j1 + j2 - v] * c_fact[j3 + m3 - v] *
                   c_fact[v + j1 - j2 - m3]);
        S += ((v + j2 + m2) & 1) ? -t : t;
    }
    return C * S;
}

__device__ __forceinline__ void qelem(int l, int r, int c, float* re, float* im) {
    int m = r - l;
    float qr = 0.f, qi = 0.f;
    const float is2 = 0.7071067811865476f;
    if (m < 0) {
        if (c == l - m) qr = is2;
        if (c == l + m) qi = -is2;
    } else if (m == 0) {
        if (c == l) qr = 1.f;
    } else {
        float sgn = (m & 1) ? -1.f : 1.f;
        if (c == l + m) qr = sgn * is2;
        if (c == l - m) qi = sgn * is2;
    }
    float pr, pi;  // (-i)^l
    switch (l & 3) {
        case 0: pr = 1.f;  pi = 0.f;  break;
        case 1: pr = 0.f;  pi = -1.f; break;
        case 2: pr = -1.f; pi = 0.f;  break;
        default: pr = 0.f; pi = 1.f;  break;
    }
    *re = pr * qr - pi * qi;
    *im = pr * qi + pi * qr;
}

// Runs inside k_init block 0 (256 threads, each covers tid, tid+256, tid+512).
__device__ void compute_w3j_block256(int tid) {
    __shared__ float sC[675];
    for (int e = tid; e < 675; e += 256) {
        int p = 0;
        for (int q = 0; q < 7; q++)
            if (e >= c_w3off[q] && e < c_w3off[q + 1]) { p = q; break; }
        int off = c_w3off[p];
        int l1 = c_l1[p], l2 = c_l2[p];
        int d1 = 2 * l1 + 1, d2 = 2 * l2 + 1;
        int li = e - off;
        int k  = li % 5;
        int i2 = (li / 5) % d2;
        int i1 = li / (5 * d2);
        float val = 0.f;
        for (int a = 0; a < d1; a++) {
            int m1 = a - l1;
            for (int b = 0; b < d2; b++) {
                int m2 = b - l2;
                int n = m1 + m2 + 2;
                if (n < 0 || n > 4) continue;
                float cg = su2_cg(l1, m1, l2, m2, 2, m1 + m2);
                if (cg == 0.f) continue;
                float q1r, q1i, q2r, q2i, q3r, q3i;
                qelem(l1, a, i1, &q1r, &q1i);
                qelem(l2, b, i2, &q2r, &q2i);
                qelem(2,  n, k,  &q3r, &q3i);
                q3i = -q3i;  // conj(Q3)
                float pr = q1r * q2r - q1i * q2i;
                float pi = q1r * q2i + q1i * q2r;
                val += cg * (pr * q3r - pi * q3i);
            }
        }
        sC[e] = val;
    }
    __syncthreads();
    for (int e = tid; e < 675; e += 256) {
        int p = 0;
        for (int q = 0; q < 7; q++)
            if (e >= c_w3off[q] && e < c_w3off[q + 1]) { p = q; break; }
        int off = c_w3off[p], tot = c_w3off[p + 1] - c_w3off[p];
        float s = 0.f;
        for (int t = 0; t < tot; t++) { float v = sC[off + t]; s += v * v; }
        g_w3j[e] = sC[e] / sqrtf(s);
    }
}

// ---------------------------------------------------------------------------
// Edge feature math
// ---------------------------------------------------------------------------
__device__ __forceinline__ void compute_sh(float x, float y, float z, float* sh) {
    float x2 = x * x, y2 = y * y, z2 = z * z;
    const float s3    = 1.7320508075688772f;
    const float s5    = 2.2360679774997896f;
    const float s15   = 3.872983346207417f;
    const float s70_4 = 2.091650066335189f;
    const float s105  = 10.246950765959598f;
    const float s42_4 = 1.6201851746019651f;
    const float s7_2  = 1.3228756555322954f;
    const float s105_2= 5.123475382979799f;
    sh[0]  = 1.f;
    sh[1]  = s3 * x;
    sh[2]  = s3 * y;
    sh[3]  = s3 * z;
    sh[4]  = s15 * x * z;
    sh[5]  = s15 * x * y;
    sh[6]  = s5 * (y2 - 0.5f * (x2 + z2));
    sh[7]  = s15 * y * z;
    sh[8]  = 0.5f * s15 * (z2 - x2);
    sh[9]  = s70_4 * x * (3.f * z2 - x2);
    sh[10] = s105 * x * y * z;
    sh[11] = s42_4 * x * (5.f * y2 - 1.f);
    sh[12] = s7_2 * y * (5.f * y2 - 3.f);
    sh[13] = s42_4 * z * (5.f * y2 - 1.f);
    sh[14] = s105_2 * y * (z2 - x2);
    sh[15] = s70_4 * z * (z2 - 3.f * x2);
}

__device__ __forceinline__ void compute_soft_onehot(float d, float* emb) {
    const float step = 3.5f / 21.f;
    const float KK = 1.14136f * 7.38905609893065f;  // 1.14136 * e^2
    for (int i = 0; i < 20; i++) {
        float v = 3.5f * (float)(i + 1) / 21.f;
        float t = (d - v) / step;
        float a = t + 1.f, b = 1.f - t;
        emb[i] = (a > 0.f && b > 0.f) ? KK * expf(-1.f / a) * expf(-1.f / b) : 0.f;
    }
}

// ---------------------------------------------------------------------------
// k_init: zero state; block 0 computes W3J
// ---------------------------------------------------------------------------
__global__ void k_init(float* __restrict__ out, int N) {
    if (blockIdx.x == 0) {
        compute_w3j_block256(threadIdx.x);
        return;
    }
    int i = (blockIdx.x - 1) * blockDim.x + threadIdx.x;
    if (i < N) { g_count[i] = 0; g_flag[i] = 0; }
    if (blockIdx.x == 1) {
        int t = threadIdx.x;
        if (t < 5) out[t] = 0.f;
        else if (t == 5) g_key = 0ull;
        else if (t == 6) g_cocount = 0;
        else if (t >= 8 && t < 12) g_bar[t - 8] = 0;
    }
}

// ---------------------------------------------------------------------------
// Global software barrier (all MEGA_BLOCKS co-resident by construction)
// ---------------------------------------------------------------------------
__device__ __forceinline__ void gbar(int i) {
    __syncthreads();
    if (threadIdx.x == 0) {
        __threadfence();
        atomicAdd(&g_bar[i], 1);
        while (atomicAdd(&g_bar[i], 0) < (int)gridDim.x) { __nanosleep(64); }
        __threadfence();
    }
    __syncthreads();
}

__device__ __forceinline__ unsigned long long packkey(int cnt, int idx) {
    return (((unsigned long long)(unsigned)cnt) << 32) | (unsigned)(~idx);
}

__device__ __forceinline__ int decode_co() {
    unsigned long long k = *((volatile unsigned long long*)&g_key);
    return (int)(~(unsigned)(k & 0xFFFFFFFFull));
}

__device__ __forceinline__ void flag_edge(int e, const int* __restrict__ eto) {
    int j = eto[e];
    g_flag[j] = 1;
    float4* z = (float4*)&g_nodemid[j * 80];
    float4 zero = make_float4(0.f, 0.f, 0.f, 0.f);
#pragma unroll
    for (int q = 0; q < 20; q++) z[q] = zero;
    int idx = atomicAdd(&g_cocount, 1);
    g_colist[idx] = e;
}

__device__ void mid_edge(int jf, int jt,
                         const float* __restrict__ x, const float* __restrict__ pos,
                         const float* __restrict__ W1, const float* __restrict__ W2) {
    float vx = pos[3 * jt + 0] - pos[3 * jf + 0];
    float vy = pos[3 * jt + 1] - pos[3 * jf + 1];
    float vz = pos[3 * jt + 2] - pos[3 * jf + 2];
    float dist = sqrtf(vx * vx + vy * vy + vz * vz);
    float inv = 1.f / dist;

    float sh[16];
    compute_sh(vx * inv, vy * inv, vz * inv, sh);
    float emb[20];
    compute_soft_onehot(dist, emb);

    float h[30];
    const float is20 = 0.22360679774997896f;
    for (int j = 0; j < 30; j++) {
        float z = 0.f;
        for (int q = 0; q < 20; q++) z += emb[q] * W1[q * 30 + j];
        z *= is20;
        h[j] = 1.679177f * z / (1.f + expf(-z));
    }
    float tp[20];
    const float is30 = 0.18257418583505536f;
    for (int k = 0; k < 20; k++) {
        float z = 0.f;
        for (int j = 0; j < 30; j++) z += h[j] * W2[j * 20 + k];
        tp[k] = z * is30;
    }

    float s = x[jt];
    const float inv6 = 0.4082482904638631f;  // 1/sqrt(6) folded in
    int base = jf * 80;
    for (int l = 0; l < 4; l++) {
        int dl = 2 * l + 1, so = l * l, mo = c_midoff[l];
        for (int u = 0; u < 5; u++) {
            float c0 = s * tp[l * 5 + u] * inv6;
            for (int m = 0; m < dl; m++)
                atomicAdd(&g_nodemid[base + mo + u * dl + m], c0 * sh[so + m]);
        }
    }
}

// ---------------------------------------------------------------------------
// Mega kernel: 4 phases, 3 global barriers, one launch
// ---------------------------------------------------------------------------
__global__ void __launch_bounds__(256, 2)
k_mega(const float* __restrict__ x, const float* __restrict__ pos,
       const int* __restrict__ efrom, const int* __restrict__ eto,
       const float* __restrict__ W1, const float* __restrict__ W2,
       const float* __restrict__ tp2w, float* __restrict__ out, int E) {
    const int gtid   = blockIdx.x * blockDim.x + threadIdx.x;
    const int stride = gridDim.x * blockDim.x;
    const int E4 = E >> 2;

    // ---- P1: histogram + fused argmax via atomicAdd return values ----
    {
        unsigned long long best = 0ull;
        for (int t = gtid; t <= E4; t += stride) {
            if (t < E4) {
                int4 v = ((const int4*)eto)[t];
                int c0 = atomicAdd(&g_count[v.x], 1) + 1;
                int c1 = atomicAdd(&g_count[v.y], 1) + 1;
                int c2 = atomicAdd(&g_count[v.z], 1) + 1;
                int c3 = atomicAdd(&g_count[v.w], 1) + 1;
                best = max(best, packkey(c0, v.x));
                best = max(best, packkey(c1, v.y));
                best = max(best, packkey(c2, v.z));
                best = max(best, packkey(c3, v.w));
            } else {
                for (int e = E4 * 4; e < E; e++) {
                    int j = eto[e];
                    int c = atomicAdd(&g_count[j], 1) + 1;
                    best = max(best, packkey(c, j));
                }
            }
        }
        for (int o = 16; o; o >>= 1)
            best = max(best, __shfl_down_sync(0xffffffff, best, o));
        __shared__ unsigned long long sm[8];
        int w = threadIdx.x >> 5;
        if ((threadIdx.x & 31) == 0) sm[w] = best;
        __syncthreads();
        if (threadIdx.x < 8) {
            best = sm[threadIdx.x];
            for (int o = 4; o; o >>= 1)
                best = max(best, __shfl_down_sync(0xff, best, o));
            if (threadIdx.x == 0) atomicMax(&g_key, best);
        }
    }
    gbar(0);

    // ---- P2: flag Co's neighbors, zero their nodemid rows, build colist ----
    {
        int co = decode_co();
        for (int t = gtid; t <= E4; t += stride) {
            if (t < E4) {
                int4 v = ((const int4*)efrom)[t];
                int e0 = 4 * t;
                if (v.x == co) flag_edge(e0,     eto);
                if (v.y == co) flag_edge(e0 + 1, eto);
                if (v.z == co) flag_edge(e0 + 2, eto);
                if (v.w == co) flag_edge(e0 + 3, eto);
            } else {
                for (int e = E4 * 4; e < E; e++)
                    if (efrom[e] == co) flag_edge(e, eto);
            }
        }
    }
    gbar(1);

    // ---- P3: scan edges; flagged sources run the MLP inline ----
    {
        for (int t = gtid; t <= E4; t += stride) {
            if (t < E4) {
                int4 v = ((const int4*)efrom)[t];
                int e0 = 4 * t;
                if (g_flag[v.x]) mid_edge(v.x, eto[e0],     x, pos, W1, W2);
                if (g_flag[v.y]) mid_edge(v.y, eto[e0 + 1], x, pos, W1, W2);
                if (g_flag[v.z]) mid_edge(v.z, eto[e0 + 2], x, pos, W1, W2);
                if (g_flag[v.w]) mid_edge(v.w, eto[e0 + 3], x, pos, W1, W2);
            } else {
                for (int e = E4 * 4; e < E; e++)
                    if (g_flag[efrom[e]]) mid_edge(efrom[e], eto[e], x, pos, W1, W2);
            }
        }
    }
    gbar(2);

    // ---- P4: final contraction over Co's edges ----
    {
        int co = decode_co();
        int n = *((volatile int*)&g_cocount);
        for (int i = gtid; i < n; i += stride) {
            int e  = g_colist[i];
            int jt = eto[e];

            float vx = pos[3 * jt + 0] - pos[3 * co + 0];
            float vy = pos[3 * jt + 1] - pos[3 * co + 1];
            float vz = pos[3 * jt + 2] - pos[3 * co + 2];
            float dist = sqrtf(vx * vx + vy * vy + vz * vz);
            float inv = 1.f / dist;
            float sh[16];
            compute_sh(vx * inv, vy * inv, vz * inv, sh);

            const float* m80 = &g_nodemid[jt * 80];
            float acc[5] = {0.f, 0.f, 0.f, 0.f, 0.f};

            for (int p = 0; p < 7; p++) {
                int l1 = c_l1[p], l2 = c_l2[p];
                int d1 = 2 * l1 + 1, d2 = 2 * l2 + 1;
                int so2 = l2 * l2, mo = c_midoff[l1], wo = c_w3off[p];
                for (int u = 0; u < 5; u++) {
                    float tw = tp2w[p * 5 + u];
                    for (int ii = 0; ii < d1; ii++) {
                        float mv = m80[mo + u * d1 + ii] * tw;
                        for (int jj = 0; jj < d2; jj++) {
                            float sv = mv * sh[so2 + jj];
                            const float* W = &g_w3j[wo + (ii * d2 + jj) * 5];
                            for (int k = 0; k < 5; k++) acc[k] += W[k] * sv;
                        }
                    }
                }
            }
            const float scale = 0.3779644730092272f * 0.4082482904638631f;  // ALPHA2/sqrt(6)
            for (int k = 0; k < 5; k++) atomicAdd(&out[k], acc[k] * scale);
        }
    }
}

// ---------------------------------------------------------------------------
// Launch
// ---------------------------------------------------------------------------
extern "C" void kernel_launch(void* const* d_in, const int* in_sizes, int n_in,
                              void* d_out, int out_size) {
    const float* x     = (const float*)d_in[0];
    const float* pos   = (const float*)d_in[1];
    const int*   efrom = (const int*)d_in[2];
    const int*   eto   = (const int*)d_in[3];
    const float* W1    = (const float*)d_in[4];
    const float* W2    = (const float*)d_in[5];
    const float* tp2w  = (const float*)d_in[6];
    float* out = (float*)d_out;

    int N = in_sizes[0];
    int E = in_sizes[2];

    int initb = 1 + (N + 255) / 256;
    k_init<<<initb, 256>>>(out, N);
    k_mega<<<MEGA_BLOCKS, 256>>>(x, pos, efrom, eto, W1, W2, tp2w, out, E);
}

// round 5
// speedup vs baseline: 1.2996x; 1.2996x over previous
#include <cuda_runtime.h>
#include <math.h>

// ---------------------------------------------------------------------------
// Scratch (__device__ globals; no runtime allocation)
// ---------------------------------------------------------------------------
#define NMAX 65536
__device__ int                 g_count[NMAX];
__device__ unsigned char       g_flag[NMAX];
__device__ __align__(16) float g_nodemid[NMAX * 80];
__device__ unsigned long long  g_key;        // (count<<32) | ~index
__device__ int                 g_cocount;
__device__ int                 g_colist[4096];
__device__ float               g_w3j[675];
__device__ int                 g_bar[4];

#define MEGA_BLOCKS 296

// Path tables: TP2_PATHS = [(0,2),(1,1),(1,3),(2,0),(2,2),(3,1),(3,3)], l3 = 2
__constant__ int c_l1[7]      = {0, 1, 1, 2, 2, 3, 3};
__constant__ int c_l2[7]      = {2, 1, 3, 0, 2, 1, 3};
__constant__ int c_w3off[8]   = {0, 25, 70, 175, 200, 325, 430, 675};
__constant__ int c_pairoff[8] = {0, 5, 14, 35, 40, 65, 86, 135};
__constant__ int c_midoff[4]  = {0, 5, 20, 45};
__constant__ float c_fact[13] = {1.f, 1.f, 2.f, 6.f, 24.f, 120.f, 720.f, 5040.f,
                                 40320.f, 362880.f, 3628800.f, 39916800.f, 479001600.f};

// ---------------------------------------------------------------------------
// Wigner 3j pieces
// ---------------------------------------------------------------------------
__device__ __forceinline__ float su2_cg(int j1, int m1, int j2, int m2, int j3, int m3) {
    if (m1 + m2 != m3) return 0.f;
    int vmin = max(max(-j1 + j2 + m3, -j1 + m1), 0);
    int vmax = min(min(j2 + j3 + m1, j3 - j1 + j2), j3 + m3);
    float C = sqrtf((2.f * j3 + 1.f) * c_fact[j3 + j1 - j2] * c_fact[j3 - j1 + j2] *
                    c_fact[j1 + j2 - j3] * c_fact[j3 + m3] * c_fact[j3 - m3] /
                    (c_fact[j1 + j2 + j3 + 1] * c_fact[j1 - m1] * c_fact[j1 + m1] *
                     c_fact[j2 - m2] * c_fact[j2 + m2]));
    float S = 0.f;
    for (int v = vmin; v <= vmax; v++) {
        float t = c_fact[j2 + j3 + m1 - v] * c_fact[j1 - m1 + v] /
                  (c_fact[v] * c_fact[j3 - j1 + j2 - v] * c_fact[j3 + m3 - v] *
                   c_fact[v + j1 - j2 - m3]);
        S += ((v + j2 + m2) & 1) ? -t : t;
    }
    return C * S;
}

__device__ __forceinline__ void qelem(int l, int r, int c, float* re, float* im) {
    int m = r - l;
    float qr = 0.f, qi = 0.f;
    const float is2 = 0.7071067811865476f;
    if (m < 0) {
        if (c == l - m) qr = is2;
        if (c == l + m) qi = -is2;
    } else if (m == 0) {
        if (c == l) qr = 1.f;
    } else {
        float sgn = (m & 1) ? -1.f : 1.f;
        if (c == l + m) qr = sgn * is2;
        if (c == l - m) qi = sgn * is2;
    }
    float pr, pi;  // (-i)^l
    switch (l & 3) {
        case 0: pr = 1.f;  pi = 0.f;  break;
        case 1: pr = 0.f;  pi = -1.f; break;
        case 2: pr = -1.f; pi = 0.f;  break;
        default: pr = 0.f; pi = 1.f;  break;
    }
    *re = pr * qr - pi * qi;
    *im = pr * qi + pi * qr;
}

// Fast W3J: CG coefficients once into smem (135 pairs), then ALU-only element
// loop, smem-atomic norms, parallel writeout. Runs on block 0 of k_mega.
__device__ void w3j_block(int tid) {
    __shared__ float sCG[135];
    __shared__ float sC[675];
    __shared__ float sNorm[7];
    if (tid < 7) sNorm[tid] = 0.f;
    if (tid < 135) {
        int p = 0;
        for (int q = 0; q < 7; q++)
            if (tid >= c_pairoff[q] && tid < c_pairoff[q + 1]) { p = q; break; }
        int l1 = c_l1[p], l2 = c_l2[p];
        int d2 = 2 * l2 + 1;
        int li = tid - c_pairoff[p];
        int a = li / d2, b = li % d2;
        int m1 = a - l1, m2 = b - l2;
        float cg = 0.f;
        if (abs(m1 + m2) <= 2) cg = su2_cg(l1, m1, l2, m2, 2, m1 + m2);
        sCG[tid] = cg;
    }
    __syncthreads();
    for (int e = tid; e < 675; e += 256) {
        int p = 0;
        for (int q = 0; q < 7; q++)
            if (e >= c_w3off[q] && e < c_w3off[q + 1]) { p = q; break; }
        int l1 = c_l1[p], l2 = c_l2[p];
        int d1 = 2 * l1 + 1, d2 = 2 * l2 + 1;
        int li = e - c_w3off[p];
        int k  = li % 5;
        int i2 = (li / 5) % d2;
        int i1 = li / (5 * d2);
        float val = 0.f;
        for (int a = 0; a < d1; a++) {
            for (int b = 0; b < d2; b++) {
                float cg = sCG[c_pairoff[p] + a * d2 + b];
                if (cg == 0.f) continue;
                int n = (a - l1) + (b - l2) + 2;
                float q1r, q1i, q2r, q2i, q3r, q3i;
                qelem(l1, a, i1, &q1r, &q1i);
                qelem(l2, b, i2, &q2r, &q2i);
                qelem(2,  n, k,  &q3r, &q3i);
                q3i = -q3i;  // conj(Q3)
                float pr = q1r * q2r - q1i * q2i;
                float pi = q1r * q2i + q1i * q2r;
                val += cg * (pr * q3r - pi * q3i);
            }
        }
        sC[e] = val;
        atomicAdd(&sNorm[p], val * val);
    }
    __syncthreads();
    for (int e = tid; e < 675; e += 256) {
        int p = 0;
        for (int q = 0; q < 7; q++)
            if (e >= c_w3off[q] && e < c_w3off[q + 1]) { p = q; break; }
        g_w3j[e] = sC[e] / sqrtf(sNorm[p]);
    }
}

// ---------------------------------------------------------------------------
// Edge feature math
// ---------------------------------------------------------------------------
__device__ __forceinline__ void compute_sh(float x, float y, float z, float* sh) {
    float x2 = x * x, y2 = y * y, z2 = z * z;
    const float s3    = 1.7320508075688772f;
    const float s5    = 2.2360679774997896f;
    const float s15   = 3.872983346207417f;
    const float s70_4 = 2.091650066335189f;
    const float s105  = 10.246950765959598f;
    const float s42_4 = 1.6201851746019651f;
    const float s7_2  = 1.3228756555322954f;
    const float s105_2= 5.123475382979799f;
    sh[0]  = 1.f;
    sh[1]  = s3 * x;
    sh[2]  = s3 * y;
    sh[3]  = s3 * z;
    sh[4]  = s15 * x * z;
    sh[5]  = s15 * x * y;
    sh[6]  = s5 * (y2 - 0.5f * (x2 + z2));
    sh[7]  = s15 * y * z;
    sh[8]  = 0.5f * s15 * (z2 - x2);
    sh[9]  = s70_4 * x * (3.f * z2 - x2);
    sh[10] = s105 * x * y * z;
    sh[11] = s42_4 * x * (5.f * y2 - 1.f);
    sh[12] = s7_2 * y * (5.f * y2 - 3.f);
    sh[13] = s42_4 * z * (5.f * y2 - 1.f);
    sh[14] = s105_2 * y * (z2 - x2);
    sh[15] = s70_4 * z * (z2 - 3.f * x2);
}

__device__ __forceinline__ void compute_soft_onehot(float d, float* emb) {
    const float step = 3.5f / 21.f;
    const float KK = 1.14136f * 7.38905609893065f;  // 1.14136 * e^2
    for (int i = 0; i < 20; i++) {
        float v = 3.5f * (float)(i + 1) / 21.f;
        float t = (d - v) / step;
        float a = t + 1.f, b = 1.f - t;
        emb[i] = (a > 0.f && b > 0.f) ? KK * expf(-1.f / a) * expf(-1.f / b) : 0.f;
    }
}

// ---------------------------------------------------------------------------
// k_init: zero state (cheap; W3J moved into k_mega)
// ---------------------------------------------------------------------------
__global__ void k_init(float* __restrict__ out, int N) {
    int i = blockIdx.x * blockDim.x + threadIdx.x;
    if (i < N) { g_count[i] = 0; g_flag[i] = 0; }
    if (blockIdx.x == 0) {
        int t = threadIdx.x;
        if (t < 5) out[t] = 0.f;
        else if (t == 5) g_key = 0ull;
        else if (t == 6) g_cocount = 0;
        else if (t >= 8 && t < 12) g_bar[t - 8] = 0;
    }
}

// ---------------------------------------------------------------------------
// Global software barrier: atomic arrival + LOAD polling (no RMW spin)
// ---------------------------------------------------------------------------
__device__ __forceinline__ void gbar(int i) {
    __syncthreads();
    if (threadIdx.x == 0) {
        __threadfence();
        atomicAdd(&g_bar[i], 1);
        volatile int* p = &g_bar[i];
        while (*p < (int)gridDim.x) { __nanosleep(128); }
        __threadfence();
    }
    __syncthreads();
}

__device__ __forceinline__ unsigned long long packkey(int cnt, int idx) {
    return (((unsigned long long)(unsigned)cnt) << 32) | (unsigned)(~idx);
}

__device__ __forceinline__ int decode_co() {
    unsigned long long k = *((volatile unsigned long long*)&g_key);
    return (int)(~(unsigned)(k & 0xFFFFFFFFull));
}

__device__ __forceinline__ void flag_edge(int e, const int* __restrict__ eto) {
    int j = eto[e];
    g_flag[j] = 1;
    float4* z = (float4*)&g_nodemid[j * 80];
    float4 zero = make_float4(0.f, 0.f, 0.f, 0.f);
#pragma unroll
    for (int q = 0; q < 20; q++) z[q] = zero;
    int idx = atomicAdd(&g_cocount, 1);
    g_colist[idx] = e;
}

__device__ void mid_edge(int jf, int jt,
                         const float* __restrict__ x, const float* __restrict__ pos,
                         const float* __restrict__ W1, const float* __restrict__ W2) {
    float vx = pos[3 * jt + 0] - pos[3 * jf + 0];
    float vy = pos[3 * jt + 1] - pos[3 * jf + 1];
    float vz = pos[3 * jt + 2] - pos[3 * jf + 2];
    float dist = sqrtf(vx * vx + vy * vy + vz * vz);
    float inv = 1.f / dist;

    float sh[16];
    compute_sh(vx * inv, vy * inv, vz * inv, sh);
    float emb[20];
    compute_soft_onehot(dist, emb);

    float h[30];
    const float is20 = 0.22360679774997896f;
    for (int j = 0; j < 30; j++) {
        float z = 0.f;
        for (int q = 0; q < 20; q++) z += emb[q] * W1[q * 30 + j];
        z *= is20;
        h[j] = 1.679177f * z / (1.f + expf(-z));
    }
    float tp[20];
    const float is30 = 0.18257418583505536f;
    for (int k = 0; k < 20; k++) {
        float z = 0.f;
        for (int j = 0; j < 30; j++) z += h[j] * W2[j * 20 + k];
        tp[k] = z * is30;
    }

    float s = x[jt];
    const float inv6 = 0.4082482904638631f;  // 1/sqrt(6) folded in
    int base = jf * 80;
    for (int l = 0; l < 4; l++) {
        int dl = 2 * l + 1, so = l * l, mo = c_midoff[l];
        for (int u = 0; u < 5; u++) {
            float c0 = s * tp[l * 5 + u] * inv6;
            for (int m = 0; m < dl; m++)
                atomicAdd(&g_nodemid[base + mo + u * dl + m], c0 * sh[so + m]);
        }
    }
}

// ---------------------------------------------------------------------------
// Mega kernel: W3J on block 0 (overlapped with P1), 4 phases, 3 barriers
// ---------------------------------------------------------------------------
__global__ void __launch_bounds__(256, 2)
k_mega(const float* __restrict__ x, const float* __restrict__ pos,
       const int* __restrict__ efrom, const int* __restrict__ eto,
       const float* __restrict__ W1, const float* __restrict__ W2,
       const float* __restrict__ tp2w, float* __restrict__ out, int E) {
    const int gtid   = blockIdx.x * blockDim.x + threadIdx.x;
    const int stride = gridDim.x * blockDim.x;
    const int E4 = E >> 2;

    // Block 0 computes W3J first (needed only in P4, hidden behind P1).
    if (blockIdx.x == 0) w3j_block(threadIdx.x);

    // ---- P1: histogram + fused argmax via atomicAdd return values ----
    {
        unsigned long long best = 0ull;
        for (int t = gtid; t <= E4; t += stride) {
            if (t < E4) {
                int4 v = ((const int4*)eto)[t];
                int c0 = atomicAdd(&g_count[v.x], 1) + 1;
                int c1 = atomicAdd(&g_count[v.y], 1) + 1;
                int c2 = atomicAdd(&g_count[v.z], 1) + 1;
                int c3 = atomicAdd(&g_count[v.w], 1) + 1;
                best = max(best, packkey(c0, v.x));
                best = max(best, packkey(c1, v.y));
                best = max(best, packkey(c2, v.z));
                best = max(best, packkey(c3, v.w));
            } else {
                for (int e = E4 * 4; e < E; e++) {
                    int j = eto[e];
                    int c = atomicAdd(&g_count[j], 1) + 1;
                    best = max(best, packkey(c, j));
                }
            }
        }
        for (int o = 16; o; o >>= 1)
            best = max(best, __shfl_down_sync(0xffffffff, best, o));
        __shared__ unsigned long long sm[8];
        int w = threadIdx.x >> 5;
        if ((threadIdx.x & 31) == 0) sm[w] = best;
        __syncthreads();
        if (threadIdx.x < 8) {
            best = sm[threadIdx.x];
            for (int o = 4; o; o >>= 1)
                best = max(best, __shfl_down_sync(0xff, best, o));
            if (threadIdx.x == 0) atomicMax(&g_key, best);
        }
    }
    gbar(0);

    // ---- P2: flag Co's neighbors, zero their nodemid rows, build colist ----
    {
        int co = decode_co();
        for (int t = gtid; t <= E4; t += stride) {
            if (t < E4) {
                int4 v = ((const int4*)efrom)[t];
                int e0 = 4 * t;
                if (v.x == co) flag_edge(e0,     eto);
                if (v.y == co) flag_edge(e0 + 1, eto);
                if (v.z == co) flag_edge(e0 + 2, eto);
                if (v.w == co) flag_edge(e0 + 3, eto);
            } else {
                for (int e = E4 * 4; e < E; e++)
                    if (efrom[e] == co) flag_edge(e, eto);
            }
        }
    }
    gbar(1);

    // ---- P3: scan edges; flagged sources run the MLP inline ----
    {
        for (int t = gtid; t <= E4; t += stride) {
            if (t < E4) {
                int4 v = ((const int4*)efrom)[t];
                int e0 = 4 * t;
                if (g_flag[v.x]) mid_edge(v.x, eto[e0],     x, pos, W1, W2);
                if (g_flag[v.y]) mid_edge(v.y, eto[e0 + 1], x, pos, W1, W2);
                if (g_flag[v.z]) mid_edge(v.z, eto[e0 + 2], x, pos, W1, W2);
                if (g_flag[v.w]) mid_edge(v.w, eto[e0 + 3], x, pos, W1, W2);
            } else {
                for (int e = E4 * 4; e < E; e++)
                    if (g_flag[efrom[e]]) mid_edge(efrom[e], eto[e], x, pos, W1, W2);
            }
        }
    }
    gbar(2);

    // ---- P4: final contraction over Co's edges ----
    {
        int co = decode_co();
        int n = *((volatile int*)&g_cocount);
        for (int i = gtid; i < n; i += stride) {
            int e  = g_colist[i];
            int jt = eto[e];

            float vx = pos[3 * jt + 0] - pos[3 * co + 0];
            float vy = pos[3 * jt + 1] - pos[3 * co + 1];
            float vz = pos[3 * jt + 2] - pos[3 * co + 2];
            float dist = sqrtf(vx * vx + vy * vy + vz * vz);
            float inv = 1.f / dist;
            float sh[16];
            compute_sh(vx * inv, vy * inv, vz * inv, sh);

            const float* m80 = &g_nodemid[jt * 80];
            float acc[5] = {0.f, 0.f, 0.f, 0.f, 0.f};

            for (int p = 0; p < 7; p++) {
                int l1 = c_l1[p], l2 = c_l2[p];
                int d1 = 2 * l1 + 1, d2 = 2 * l2 + 1;
                int so2 = l2 * l2, mo = c_midoff[l1], wo = c_w3off[p];
                for (int u = 0; u < 5; u++) {
                    float tw = tp2w[p * 5 + u];
                    for (int ii = 0; ii < d1; ii++) {
                        float mv = m80[mo + u * d1 + ii] * tw;
                        for (int jj = 0; jj < d2; jj++) {
                            float sv = mv * sh[so2 + jj];
                            const float* W = &g_w3j[wo + (ii * d2 + jj) * 5];
                            for (int k = 0; k < 5; k++) acc[k] += W[k] * sv;
                        }
                    }
                }
            }
            const float scale = 0.3779644730092272f * 0.4082482904638631f;  // ALPHA2/sqrt(6)
            for (int k = 0; k < 5; k++) atomicAdd(&out[k], acc[k] * scale);
        }
    }
}

// ---------------------------------------------------------------------------
// Launch
// ---------------------------------------------------------------------------
extern "C" void kernel_launch(void* const* d_in, const int* in_sizes, int n_in,
                              void* d_out, int out_size) {
    const float* x     = (const float*)d_in[0];
    const float* pos   = (const float*)d_in[1];
    const int*   efrom = (const int*)d_in[2];
    const int*   eto   = (const int*)d_in[3];
    const float* W1    = (const float*)d_in[4];
    const float* W2    = (const float*)d_in[5];
    const float* tp2w  = (const float*)d_in[6];
    float* out = (float*)d_out;

    int N = in_sizes[0];
    int E = in_sizes[2];

    int initb = (N + 255) / 256;
    k_init<<<initb, 256>>>(out, N);
    k_mega<<<MEGA_BLOCKS, 256>>>(x, pos, efrom, eto, W1, W2, tp2w, out, E);
}

// round 6
// speedup vs baseline: 1.8030x; 1.3873x over previous
#include <cuda_runtime.h>
#include <math.h>

// ---------------------------------------------------------------------------
// Scratch (__device__ globals; no runtime allocation)
// ---------------------------------------------------------------------------
#define NMAX 65536
__device__ int                 g_count[NMAX];
__device__ unsigned char       g_flag[NMAX];
__device__ __align__(16) float g_nodemid[NMAX * 80];
__device__ unsigned long long  g_key;        // (count<<32) | ~index
__device__ int                 g_cocount;
__device__ int                 g_colist[4096];
__device__ float               g_w3j[675];
__device__ int                 g_bar[4];

#define MEGA_BLOCKS 296

// Path tables: TP2_PATHS = [(0,2),(1,1),(1,3),(2,0),(2,2),(3,1),(3,3)], l3 = 2
__constant__ int c_l1[7]      = {0, 1, 1, 2, 2, 3, 3};
__constant__ int c_l2[7]      = {2, 1, 3, 0, 2, 1, 3};
__constant__ int c_w3off[8]   = {0, 25, 70, 175, 200, 325, 430, 675};
__constant__ int c_pairoff[8] = {0, 5, 14, 35, 40, 65, 86, 135};
__constant__ int c_midoff[4]  = {0, 5, 20, 45};
__constant__ int c_qoff[4]    = {0, 1, 10, 35};   // offsets of Q_l tables (sizes 1,9,25,49)
__constant__ float c_fact[13] = {1.f, 1.f, 2.f, 6.f, 24.f, 120.f, 720.f, 5040.f,
                                 40320.f, 362880.f, 3628800.f, 39916800.f, 479001600.f};

// ---------------------------------------------------------------------------
// Wigner 3j pieces
// ---------------------------------------------------------------------------
__device__ __forceinline__ float su2_cg(int j1, int m1, int j2, int m2, int j3, int m3) {
    if (m1 + m2 != m3) return 0.f;
    int vmin = max(max(-j1 + j2 + m3, -j1 + m1), 0);
    int vmax = min(min(j2 + j3 + m1, j3 - j1 + j2), j3 + m3);
    float C = sqrtf((2.f * j3 + 1.f) * c_fact[j3 + j1 - j2] * c_fact[j3 - j1 + j2] *
                    c_fact[j1 + j2 - j3] * c_fact[j3 + m3] * c_fact[j3 - m3] /
                    (c_fact[j1 + j2 + j3 + 1] * c_fact[j1 - m1] * c_fact[j1 + m1] *
                     c_fact[j2 - m2] * c_fact[j2 + m2]));
    float S = 0.f;
    for (int v = vmin; v <= vmax; v++) {
        float t = c_fact[j2 + j3 + m1 - v] * c_fact[j1 - m1 + v] /
                  (c_fact[v] * c_fact[j3 - j1 + j2 - v] * c_fact[j3 + m3 - v] *
                   c_fact[v + j1 - j2 - m3]);
        S += ((v + j2 + m2) & 1) ? -t : t;
    }
    return C * S;
}

// Element (row r, col c) of Q_l = (-i)^l * q_l  (executed once per table entry)
__device__ __forceinline__ void qelem(int l, int r, int c, float* re, float* im) {
    int m = r - l;
    float qr = 0.f, qi = 0.f;
    const float is2 = 0.7071067811865476f;
    if (m < 0) {
        if (c == l - m) qr = is2;
        if (c == l + m) qi = -is2;
    } else if (m == 0) {
        if (c == l) qr = 1.f;
    } else {
        float sgn = (m & 1) ? -1.f : 1.f;
        if (c == l + m) qr = sgn * is2;
        if (c == l - m) qi = sgn * is2;
    }
    float pr, pi;  // (-i)^l
    switch (l & 3) {
        case 0: pr = 1.f;  pi = 0.f;  break;
        case 1: pr = 0.f;  pi = -1.f; break;
        case 2: pr = -1.f; pi = 0.f;  break;
        default: pr = 0.f; pi = 1.f;  break;
    }
    *re = pr * qr - pi * qi;
    *im = pr * qi + pi * qr;
}

// Fast W3J: Q_l matrices built ONCE into smem (84 entries, one qelem each),
// CG coefficients once into smem (135), then the 675-element loop is pure
// LDS+FMA. Runs on block 0 of k_mega, overlapped with P1.
__device__ void w3j_block(int tid) {
    __shared__ float2 sQ[84];     // Q_l tables: offsets {0,1,10,35}
    __shared__ float  sCG[135];
    __shared__ float  sC[675];
    __shared__ float  sNorm[7];
    if (tid < 7) sNorm[tid] = 0.f;
    if (tid < 84) {
        int l = (tid >= 35) ? 3 : (tid >= 10) ? 2 : (tid >= 1) ? 1 : 0;
        int li = tid - c_qoff[l];
        int d = 2 * l + 1;
        int r = li / d, c = li % d;
        float re, im;
        qelem(l, r, c, &re, &im);
        sQ[tid] = make_float2(re, im);
    }
    if (tid >= 96 && tid < 96 + 135) {
        int t = tid - 96;
        int p = 0;
        for (int q = 0; q < 7; q++)
            if (t >= c_pairoff[q] && t < c_pairoff[q + 1]) { p = q; break; }
        int l1 = c_l1[p], l2 = c_l2[p];
        int d2 = 2 * l2 + 1;
        int li = t - c_pairoff[p];
        int a = li / d2, b = li % d2;
        int m1 = a - l1, m2 = b - l2;
        float cg = 0.f;
        if (abs(m1 + m2) <= 2) cg = su2_cg(l1, m1, l2, m2, 2, m1 + m2);
        sCG[t] = cg;
    }
    __syncthreads();
    for (int e = tid; e < 675; e += 256) {
        int p = 0;
        for (int q = 0; q < 7; q++)
            if (e >= c_w3off[q] && e < c_w3off[q + 1]) { p = q; break; }
        int l1 = c_l1[p], l2 = c_l2[p];
        int d1 = 2 * l1 + 1, d2 = 2 * l2 + 1;
        int li = e - c_w3off[p];
        int k  = li % 5;
        int i2 = (li / 5) % d2;
        int i1 = li / (5 * d2);
        const float2* Q1 = &sQ[c_qoff[l1]];
        const float2* Q2 = &sQ[c_qoff[l2]];
        const float2* Q3 = &sQ[c_qoff[2]];
        const float*  CG = &sCG[c_pairoff[p]];
        float val = 0.f;
        for (int a = 0; a < d1; a++) {
            float2 q1 = Q1[a * d1 + i1];
            for (int b = 0; b < d2; b++) {
                float cg = CG[a * d2 + b];
                if (cg == 0.f) continue;
                int n = (a - l1) + (b - l2) + 2;
                float2 q2 = Q2[b * d2 + i2];
                float2 q3 = Q3[n * 5 + k];
                float pr = q1.x * q2.x - q1.y * q2.y;
                float pi = q1.x * q2.y + q1.y * q2.x;
                val += cg * (pr * q3.x + pi * q3.y);  // Re[p * conj(q3)]
            }
        }
        sC[e] = val;
        atomicAdd(&sNorm[p], val * val);
    }
    __syncthreads();
    for (int e = tid; e < 675; e += 256) {
        int p = 0;
        for (int q = 0; q < 7; q++)
            if (e >= c_w3off[q] && e < c_w3off[q + 1]) { p = q; break; }
        g_w3j[e] = sC[e] / sqrtf(sNorm[p]);
    }
}

// ---------------------------------------------------------------------------
// Edge feature math
// ---------------------------------------------------------------------------
__device__ __forceinline__ void compute_sh(float x, float y, float z, float* sh) {
    float x2 = x * x, y2 = y * y, z2 = z * z;
    const float s3    = 1.7320508075688772f;
    const float s5    = 2.2360679774997896f;
    const float s15   = 3.872983346207417f;
    const float s70_4 = 2.091650066335189f;
    const float s105  = 10.246950765959598f;
    const float s42_4 = 1.6201851746019651f;
    const float s7_2  = 1.3228756555322954f;
    const float s105_2= 5.123475382979799f;
    sh[0]  = 1.f;
    sh[1]  = s3 * x;
    sh[2]  = s3 * y;
    sh[3]  = s3 * z;
    sh[4]  = s15 * x * z;
    sh[5]  = s15 * x * y;
    sh[6]  = s5 * (y2 - 0.5f * (x2 + z2));
    sh[7]  = s15 * y * z;
    sh[8]  = 0.5f * s15 * (z2 - x2);
    sh[9]  = s70_4 * x * (3.f * z2 - x2);
    sh[10] = s105 * x * y * z;
    sh[11] = s42_4 * x * (5.f * y2 - 1.f);
    sh[12] = s7_2 * y * (5.f * y2 - 3.f);
    sh[13] = s42_4 * z * (5.f * y2 - 1.f);
    sh[14] = s105_2 * y * (z2 - x2);
    sh[15] = s70_4 * z * (z2 - 3.f * x2);
}

__device__ __forceinline__ void compute_soft_onehot(float d, float* emb) {
    const float step = 3.5f / 21.f;
    const float KK = 1.14136f * 7.38905609893065f;  // 1.14136 * e^2
    for (int i = 0; i < 20; i++) {
        float v = 3.5f * (float)(i + 1) / 21.f;
        float t = (d - v) / step;
        float a = t + 1.f, b = 1.f - t;
        emb[i] = (a > 0.f && b > 0.f) ? KK * expf(-1.f / a) * expf(-1.f / b) : 0.f;
    }
}

// ---------------------------------------------------------------------------
// k_init: zero state
// ---------------------------------------------------------------------------
__global__ void k_init(float* __restrict__ out, int N) {
    int t = blockIdx.x * blockDim.x + threadIdx.x;
    int N4 = (N + 3) >> 2;
    if (t < N4) {
        ((int4*)g_count)[t] = make_int4(0, 0, 0, 0);
        ((int*)g_flag)[t]   = 0;  // 4 bytes of flags
    }
    if (blockIdx.x == 0) {
        int i = threadIdx.x;
        if (i < 5) out[i] = 0.f;
        else if (i == 5) g_key = 0ull;
        else if (i == 6) g_cocount = 0;
        else if (i >= 8 && i < 12) g_bar[i - 8] = 0;
    }
}

// ---------------------------------------------------------------------------
// Global software barrier: atomic arrival + LOAD polling
// ---------------------------------------------------------------------------
__device__ __forceinline__ void gbar(int i) {
    __syncthreads();
    if (threadIdx.x == 0) {
        __threadfence();
        atomicAdd(&g_bar[i], 1);
        volatile int* p = &g_bar[i];
        while (*p < (int)gridDim.x) { __nanosleep(128); }
        __threadfence();
    }
    __syncthreads();
}

__device__ __forceinline__ unsigned long long packkey(int cnt, int idx) {
    return (((unsigned long long)(unsigned)cnt) << 32) | (unsigned)(~idx);
}

__device__ __forceinline__ int decode_co() {
    unsigned long long k = *((volatile unsigned long long*)&g_key);
    return (int)(~(unsigned)(k & 0xFFFFFFFFull));
}

__device__ __forceinline__ void flag_edge(int e, const int* __restrict__ eto) {
    int j = eto[e];
    g_flag[j] = 1;
    float4* z = (float4*)&g_nodemid[j * 80];
    float4 zero = make_float4(0.f, 0.f, 0.f, 0.f);
#pragma unroll
    for (int q = 0; q < 20; q++) z[q] = zero;
    int idx = atomicAdd(&g_cocount, 1);
    g_colist[idx] = e;
}

__device__ void mid_edge(int jf, int jt,
                         const float* __restrict__ x, const float* __restrict__ pos,
                         const float* __restrict__ W1, const float* __restrict__ W2) {
    float vx = pos[3 * jt + 0] - pos[3 * jf + 0];
    float vy = pos[3 * jt + 1] - pos[3 * jf + 1];
    float vz = pos[3 * jt + 2] - pos[3 * jf + 2];
    float dist = sqrtf(vx * vx + vy * vy + vz * vz);
    float inv = 1.f / dist;

    float sh[16];
    compute_sh(vx * inv, vy * inv, vz * inv, sh);
    float emb[20];
    compute_soft_onehot(dist, emb);

    float h[30];
    const float is20 = 0.22360679774997896f;
    for (int j = 0; j < 30; j++) {
        float z = 0.f;
        for (int q = 0; q < 20; q++) z += emb[q] * W1[q * 30 + j];
        z *= is20;
        h[j] = 1.679177f * z / (1.f + expf(-z));
    }
    float tp[20];
    const float is30 = 0.18257418583505536f;
    for (int k = 0; k < 20; k++) {
        float z = 0.f;
        for (int j = 0; j < 30; j++) z += h[j] * W2[j * 20 + k];
        tp[k] = z * is30;
    }

    float s = x[jt];
    const float inv6 = 0.4082482904638631f;  // 1/sqrt(6) folded in
    int base = jf * 80;
    for (int l = 0; l < 4; l++) {
        int dl = 2 * l + 1, so = l * l, mo = c_midoff[l];
        for (int u = 0; u < 5; u++) {
            float c0 = s * tp[l * 5 + u] * inv6;
            for (int m = 0; m < dl; m++)
                atomicAdd(&g_nodemid[base + mo + u * dl + m], c0 * sh[so + m]);
        }
    }
}

// ---------------------------------------------------------------------------
// Mega kernel: W3J on block 0 (overlapped with P1), 4 phases, 3 barriers
// ---------------------------------------------------------------------------
__global__ void __launch_bounds__(256, 2)
k_mega(const float* __restrict__ x, const float* __restrict__ pos,
       const int* __restrict__ efrom, const int* __restrict__ eto,
       const float* __restrict__ W1, const float* __restrict__ W2,
       const float* __restrict__ tp2w, float* __restrict__ out, int E) {
    const int gtid   = blockIdx.x * blockDim.x + threadIdx.x;
    const int stride = gridDim.x * blockDim.x;
    const int E4 = E >> 2;

    // Block 0 computes W3J (cheap now; needed only in P4).
    if (blockIdx.x == 0) w3j_block(threadIdx.x);

    // ---- P1: histogram + fused argmax via atomicAdd return values ----
    {
        unsigned long long best = 0ull;
        for (int t = gtid; t <= E4; t += stride) {
            if (t < E4) {
                int4 v = ((const int4*)eto)[t];
                int c0 = atomicAdd(&g_count[v.x], 1) + 1;
                int c1 = atomicAdd(&g_count[v.y], 1) + 1;
                int c2 = atomicAdd(&g_count[v.z], 1) + 1;
                int c3 = atomicAdd(&g_count[v.w], 1) + 1;
                best = max(best, packkey(c0, v.x));
                best = max(best, packkey(c1, v.y));
                best = max(best, packkey(c2, v.z));
                best = max(best, packkey(c3, v.w));
            } else {
                for (int e = E4 * 4; e < E; e++) {
                    int j = eto[e];
                    int c = atomicAdd(&g_count[j], 1) + 1;
                    best = max(best, packkey(c, j));
                }
            }
        }
        for (int o = 16; o; o >>= 1)
            best = max(best, __shfl_down_sync(0xffffffff, best, o));
        __shared__ unsigned long long sm[8];
        int w = threadIdx.x >> 5;
        if ((threadIdx.x & 31) == 0) sm[w] = best;
        __syncthreads();
        if (threadIdx.x < 8) {
            best = sm[threadIdx.x];
            for (int o = 4; o; o >>= 1)
                best = max(best, __shfl_down_sync(0xff, best, o));
            if (threadIdx.x == 0) atomicMax(&g_key, best);
        }
    }
    gbar(0);

    // ---- P2: flag Co's neighbors, zero their nodemid rows, build colist ----
    {
        int co = decode_co();
        for (int t = gtid; t <= E4; t += stride) {
            if (t < E4) {
                int4 v = ((const int4*)efrom)[t];
                int e0 = 4 * t;
                if (v.x == co) flag_edge(e0,     eto);
                if (v.y == co) flag_edge(e0 + 1, eto);
                if (v.z == co) flag_edge(e0 + 2, eto);
                if (v.w == co) flag_edge(e0 + 3, eto);
            } else {
                for (int e = E4 * 4; e < E; e++)
                    if (efrom[e] == co) flag_edge(e, eto);
            }
        }
    }
    gbar(1);

    // ---- P3: scan edges; flagged sources run the MLP inline ----
    {
        for (int t = gtid; t <= E4; t += stride) {
            if (t < E4) {
                int4 v = ((const int4*)efrom)[t];
                int e0 = 4 * t;
                if (g_flag[v.x]) mid_edge(v.x, eto[e0],     x, pos, W1, W2);
                if (g_flag[v.y]) mid_edge(v.y, eto[e0 + 1], x, pos, W1, W2);
                if (g_flag[v.z]) mid_edge(v.z, eto[e0 + 2], x, pos, W1, W2);
                if (g_flag[v.w]) mid_edge(v.w, eto[e0 + 3], x, pos, W1, W2);
            } else {
                for (int e = E4 * 4; e < E; e++)
                    if (g_flag[efrom[e]]) mid_edge(efrom[e], eto[e], x, pos, W1, W2);
            }
        }
    }
    gbar(2);

    // ---- P4: final contraction over Co's edges, parallel over (edge, u) ----
    {
        int co = decode_co();
        int n = *((volatile int*)&g_cocount);
        int tot = n * 5;
        for (int w = gtid; w < tot; w += stride) {
            int i = w / 5, u = w % 5;
            int e  = g_colist[i];
            int jt = eto[e];

            float vx = pos[3 * jt + 0] - pos[3 * co + 0];
            float vy = pos[3 * jt + 1] - pos[3 * co + 1];
            float vz = pos[3 * jt + 2] - pos[3 * co + 2];
            float dist = sqrtf(vx * vx + vy * vy + vz * vz);
            float inv = 1.f / dist;
            float sh[16];
            compute_sh(vx * inv, vy * inv, vz * inv, sh);

            const float* m80 = &g_nodemid[jt * 80];
            float acc[5] = {0.f, 0.f, 0.f, 0.f, 0.f};

            for (int p = 0; p < 7; p++) {
                int l1 = c_l1[p], l2 = c_l2[p];
                int d1 = 2 * l1 + 1, d2 = 2 * l2 + 1;
                int so2 = l2 * l2, mo = c_midoff[l1], wo = c_w3off[p];
                float tw = tp2w[p * 5 + u];
                for (int ii = 0; ii < d1; ii++) {
                    float mv = m80[mo + u * d1 + ii] * tw;
                    for (int jj = 0; jj < d2; jj++) {
                        float sv = mv * sh[so2 + jj];
                        const float* W = &g_w3j[wo + (ii * d2 + jj) * 5];
                        for (int k = 0; k < 5; k++) acc[k] += W[k] * sv;
                    }
                }
            }
            const float scale = 0.3779644730092272f * 0.4082482904638631f;  // ALPHA2/sqrt(6)
            for (int k = 0; k < 5; k++) atomicAdd(&out[k], acc[k] * scale);
        }
    }
}

// ---------------------------------------------------------------------------
// Launch
// ---------------------------------------------------------------------------
extern "C" void kernel_launch(void* const* d_in, const int* in_sizes, int n_in,
                              void* d_out, int out_size) {
    const float* x     = (const float*)d_in[0];
    const float* pos   = (const float*)d_in[1];
    const int*   efrom = (const int*)d_in[2];
    const int*   eto   = (const int*)d_in[3];
    const float* W1    = (const float*)d_in[4];
    const float* W2    = (const float*)d_in[5];
    const float* tp2w  = (const float*)d_in[6];
    float* out = (float*)d_out;

    int N = in_sizes[0];
    int E = in_sizes[2];

    int initb = ((N + 3) / 4 + 255) / 256;
    k_init<<<initb, 256>>>(out, N);
    k_mega<<<MEGA_BLOCKS, 256>>>(x, pos, efrom, eto, W1, W2, tp2w, out, E);
}

// round 7
// speedup vs baseline: 1.8482x; 1.0251x over previous
#include <cuda_runtime.h>
#include <math.h>

// ---------------------------------------------------------------------------
// Scratch (__device__ globals; no runtime allocation)
// ---------------------------------------------------------------------------
#define NMAX 65536
__device__ int                 g_count[NMAX];
__device__ unsigned char       g_flag[NMAX];
__device__ __align__(16) float g_nodemid[NMAX * 80];
__device__ unsigned long long  g_key;        // (count<<32) | ~index
__device__ int                 g_cocount;
__device__ int                 g_colist[4096];
__device__ float               g_w3j[675];
__device__ int                 g_bar[4];

#define MEGA_BLOCKS 296

// Path tables: TP2_PATHS = [(0,2),(1,1),(1,3),(2,0),(2,2),(3,1),(3,3)], l3 = 2
__constant__ int c_l1[7]      = {0, 1, 1, 2, 2, 3, 3};
__constant__ int c_l2[7]      = {2, 1, 3, 0, 2, 1, 3};
__constant__ int c_w3off[8]   = {0, 25, 70, 175, 200, 325, 430, 675};
__constant__ int c_pairoff[8] = {0, 5, 14, 35, 40, 65, 86, 135};
__constant__ int c_midoff[4]  = {0, 5, 20, 45};
__constant__ int c_qoff[4]    = {0, 1, 10, 35};   // Q_l table offsets (sizes 1,9,25,49)
__constant__ float c_fact[13] = {1.f, 1.f, 2.f, 6.f, 24.f, 120.f, 720.f, 5040.f,
                                 40320.f, 362880.f, 3628800.f, 39916800.f, 479001600.f};

// ---------------------------------------------------------------------------
// Wigner 3j pieces
// ---------------------------------------------------------------------------
__device__ __forceinline__ float su2_cg(int j1, int m1, int j2, int m2, int j3, int m3) {
    if (m1 + m2 != m3) return 0.f;
    int vmin = max(max(-j1 + j2 + m3, -j1 + m1), 0);
    int vmax = min(min(j2 + j3 + m1, j3 - j1 + j2), j3 + m3);
    float C = sqrtf((2.f * j3 + 1.f) * c_fact[j3 + j1 - j2] * c_fact[j3 - j1 + j2] *
                    c_fact[j1 + j2 - j3] * c_fact[j3 + m3] * c_fact[j3 - m3] /
                    (c_fact[j1 + j2 + j3 + 1] * c_fact[j1 - m1] * c_fact[j1 + m1] *
                     c_fact[j2 - m2] * c_fact[j2 + m2]));
    float S = 0.f;
    for (int v = vmin; v <= vmax; v++) {
        float t = c_fact[j2 + j3 + m1 - v] * c_fact[j1 - m1 + v] /
                  (c_fact[v] * c_fact[j3 - j1 + j2 - v] * c_fact[j3 + m3 - v] *
                   c_fact[v + j1 - j2 - m3]);
        S += ((v + j2 + m2) & 1) ? -t : t;
    }
    return C * S;
}

// Element (row r, col c) of Q_l = (-i)^l * q_l  (executed once per table entry)
__device__ __forceinline__ void qelem(int l, int r, int c, float* re, float* im) {
    int m = r - l;
    float qr = 0.f, qi = 0.f;
    const float is2 = 0.7071067811865476f;
    if (m < 0) {
        if (c == l - m) qr = is2;
        if (c == l + m) qi = -is2;
    } else if (m == 0) {
        if (c == l) qr = 1.f;
    } else {
        float sgn = (m & 1) ? -1.f : 1.f;
        if (c == l + m) qr = sgn * is2;
        if (c == l - m) qi = sgn * is2;
    }
    float pr, pi;  // (-i)^l
    switch (l & 3) {
        case 0: pr = 1.f;  pi = 0.f;  break;
        case 1: pr = 0.f;  pi = -1.f; break;
        case 2: pr = -1.f; pi = 0.f;  break;
        default: pr = 0.f; pi = 1.f;  break;
    }
    *re = pr * qr - pi * qi;
    *im = pr * qi + pi * qr;
}

// W3J on one block: Q tables + CG into smem once, pure LDS+FMA element loop,
// warp-shuffle norms (no contended smem atomics).
__device__ void w3j_block(int tid) {
    __shared__ float2 sQ[84];
    __shared__ float  sCG[135];
    __shared__ float  sC[675];
    __shared__ float  sNorm[7];
    if (tid < 84) {
        int l = (tid >= 35) ? 3 : (tid >= 10) ? 2 : (tid >= 1) ? 1 : 0;
        int li = tid - c_qoff[l];
        int d = 2 * l + 1;
        float re, im;
        qelem(l, li / d, li % d, &re, &im);
        sQ[tid] = make_float2(re, im);
    }
    if (tid >= 96 && tid < 96 + 135) {
        int t = tid - 96;
        int p = 0;
        for (int q = 0; q < 7; q++)
            if (t >= c_pairoff[q] && t < c_pairoff[q + 1]) { p = q; break; }
        int l1 = c_l1[p], l2 = c_l2[p];
        int d2 = 2 * l2 + 1;
        int li = t - c_pairoff[p];
        int a = li / d2, b = li % d2;
        int m1 = a - l1, m2 = b - l2;
        float cg = 0.f;
        if (abs(m1 + m2) <= 2) cg = su2_cg(l1, m1, l2, m2, 2, m1 + m2);
        sCG[t] = cg;
    }
    __syncthreads();
    for (int e = tid; e < 675; e += 256) {
        int p = 0;
        for (int q = 0; q < 7; q++)
            if (e >= c_w3off[q] && e < c_w3off[q + 1]) { p = q; break; }
        int l1 = c_l1[p], l2 = c_l2[p];
        int d1 = 2 * l1 + 1, d2 = 2 * l2 + 1;
        int li = e - c_w3off[p];
        int k  = li % 5;
        int i2 = (li / 5) % d2;
        int i1 = li / (5 * d2);
        const float2* Q1 = &sQ[c_qoff[l1]];
        const float2* Q2 = &sQ[c_qoff[l2]];
        const float2* Q3 = &sQ[c_qoff[2]];
        const float*  CG = &sCG[c_pairoff[p]];
        float val = 0.f;
        for (int a = 0; a < d1; a++) {
            float2 q1 = Q1[a * d1 + i1];
            for (int b = 0; b < d2; b++) {
                float cg = CG[a * d2 + b];
                if (cg == 0.f) continue;
                int n = (a - l1) + (b - l2) + 2;
                float2 q2 = Q2[b * d2 + i2];
                float2 q3 = Q3[n * 5 + k];
                float pr = q1.x * q2.x - q1.y * q2.y;
                float pi = q1.x * q2.y + q1.y * q2.x;
                val += cg * (pr * q3.x + pi * q3.y);  // Re[p * conj(q3)]
            }
        }
        sC[e] = val;
    }
    __syncthreads();
    // warp w (<7) reduces path w's norm
    int w = tid >> 5, lane = tid & 31;
    if (w < 7) {
        int off = c_w3off[w], tot = c_w3off[w + 1] - off;
        float s = 0.f;
        for (int t = lane; t < tot; t += 32) { float v = sC[off + t]; s += v * v; }
        for (int o = 16; o; o >>= 1) s += __shfl_down_sync(0xffffffff, s, o);
        if (lane == 0) sNorm[w] = sqrtf(s);
    }
    __syncthreads();
    for (int e = tid; e < 675; e += 256) {
        int p = 0;
        for (int q = 0; q < 7; q++)
            if (e >= c_w3off[q] && e < c_w3off[q + 1]) { p = q; break; }
        g_w3j[e] = sC[e] / sNorm[p];
    }
}

// ---------------------------------------------------------------------------
// Edge feature math
// ---------------------------------------------------------------------------
__device__ __forceinline__ void compute_sh(float x, float y, float z, float* sh) {
    float x2 = x * x, y2 = y * y, z2 = z * z;
    const float s3    = 1.7320508075688772f;
    const float s5    = 2.2360679774997896f;
    const float s15   = 3.872983346207417f;
    const float s70_4 = 2.091650066335189f;
    const float s105  = 10.246950765959598f;
    const float s42_4 = 1.6201851746019651f;
    const float s7_2  = 1.3228756555322954f;
    const float s105_2= 5.123475382979799f;
    sh[0]  = 1.f;
    sh[1]  = s3 * x;
    sh[2]  = s3 * y;
    sh[3]  = s3 * z;
    sh[4]  = s15 * x * z;
    sh[5]  = s15 * x * y;
    sh[6]  = s5 * (y2 - 0.5f * (x2 + z2));
    sh[7]  = s15 * y * z;
    sh[8]  = 0.5f * s15 * (z2 - x2);
    sh[9]  = s70_4 * x * (3.f * z2 - x2);
    sh[10] = s105 * x * y * z;
    sh[11] = s42_4 * x * (5.f * y2 - 1.f);
    sh[12] = s7_2 * y * (5.f * y2 - 3.f);
    sh[13] = s42_4 * z * (5.f * y2 - 1.f);
    sh[14] = s105_2 * y * (z2 - x2);
    sh[15] = s70_4 * z * (z2 - 3.f * x2);
}

__device__ __forceinline__ void compute_soft_onehot(float d, float* emb) {
    const float step = 3.5f / 21.f;
    const float KK = 1.14136f * 7.38905609893065f;  // 1.14136 * e^2
    for (int i = 0; i < 20; i++) {
        float v = 3.5f * (float)(i + 1) / 21.f;
        float t = (d - v) / step;
        float a = t + 1.f, b = 1.f - t;
        emb[i] = (a > 0.f && b > 0.f) ? KK * expf(-1.f / a) * expf(-1.f / b) : 0.f;
    }
}

// ---------------------------------------------------------------------------
// k_init: zero state
// ---------------------------------------------------------------------------
__global__ void k_init(float* __restrict__ out, int N) {
    int t = blockIdx.x * blockDim.x + threadIdx.x;
    int N4 = (N + 3) >> 2;
    if (t < N4) {
        ((int4*)g_count)[t] = make_int4(0, 0, 0, 0);
        ((int*)g_flag)[t]   = 0;
    }
    if (blockIdx.x == 0) {
        int i = threadIdx.x;
        if (i < 5) out[i] = 0.f;
        else if (i == 5) g_key = 0ull;
        else if (i == 6) g_cocount = 0;
        else if (i >= 8 && i < 12) g_bar[i - 8] = 0;
    }
}

// ---------------------------------------------------------------------------
// Global software barrier: atomic arrival + LOAD polling
// ---------------------------------------------------------------------------
__device__ __forceinline__ void gbar(int i) {
    __syncthreads();
    if (threadIdx.x == 0) {
        __threadfence();
        atomicAdd(&g_bar[i], 1);
        volatile int* p = &g_bar[i];
        while (*p < (int)gridDim.x) { __nanosleep(64); }
        __threadfence();
    }
    __syncthreads();
}

__device__ __forceinline__ unsigned long long packkey(int cnt, int idx) {
    return (((unsigned long long)(unsigned)cnt) << 32) | (unsigned)(~idx);
}

__device__ __forceinline__ int decode_co() {
    unsigned long long k = *((volatile unsigned long long*)&g_key);
    return (int)(~(unsigned)(k & 0xFFFFFFFFull));
}

__device__ __forceinline__ void flag_edge(int e, const int* __restrict__ eto) {
    int j = eto[e];
    g_flag[j] = 1;
    float4* z = (float4*)&g_nodemid[j * 80];
    float4 zero = make_float4(0.f, 0.f, 0.f, 0.f);
#pragma unroll
    for (int q = 0; q < 20; q++) z[q] = zero;
    int idx = atomicAdd(&g_cocount, 1);
    g_colist[idx] = e;
}

__device__ void mid_edge(int jf, int jt,
                         const float* __restrict__ x, const float* __restrict__ pos,
                         const float* __restrict__ W1, const float* __restrict__ W2) {
    float vx = pos[3 * jt + 0] - pos[3 * jf + 0];
    float vy = pos[3 * jt + 1] - pos[3 * jf + 1];
    float vz = pos[3 * jt + 2] - pos[3 * jf + 2];
    float dist = sqrtf(vx * vx + vy * vy + vz * vz);
    float inv = 1.f / dist;

    float sh[16];
    compute_sh(vx * inv, vy * inv, vz * inv, sh);
    float emb[20];
    compute_soft_onehot(dist, emb);

    float h[30];
    const float is20 = 0.22360679774997896f;
    for (int j = 0; j < 30; j++) {
        float z = 0.f;
        for (int q = 0; q < 20; q++) z += emb[q] * W1[q * 30 + j];
        z *= is20;
        h[j] = 1.679177f * z / (1.f + expf(-z));
    }
    float tp[20];
    const float is30 = 0.18257418583505536f;
    for (int k = 0; k < 20; k++) {
        float z = 0.f;
        for (int j = 0; j < 30; j++) z += h[j] * W2[j * 20 + k];
        tp[k] = z * is30;
    }

    float s = x[jt];
    const float inv6 = 0.4082482904638631f;  // 1/sqrt(6) folded in
    int base = jf * 80;
    for (int l = 0; l < 4; l++) {
        int dl = 2 * l + 1, so = l * l, mo = c_midoff[l];
        for (int u = 0; u < 5; u++) {
            float c0 = s * tp[l * 5 + u] * inv6;
            for (int m = 0; m < dl; m++)
                atomicAdd(&g_nodemid[base + mo + u * dl + m], c0 * sh[so + m]);
        }
    }
}

// ---------------------------------------------------------------------------
// Mega kernel: 5 phases, 4 barriers. Block 0 does W3J while 1..295 do P1.
// ---------------------------------------------------------------------------
__global__ void __launch_bounds__(256, 2)
k_mega(const float* __restrict__ x, const float* __restrict__ pos,
       const int* __restrict__ efrom, const int* __restrict__ eto,
       const float* __restrict__ W1, const float* __restrict__ W2,
       const float* __restrict__ tp2w, float* __restrict__ out, int E, int N) {
    const int gtid   = blockIdx.x * blockDim.x + threadIdx.x;
    const int stride = gridDim.x * blockDim.x;
    const int E4 = E >> 2;
    const int Etail = E - E4 * 4;

    // ---- P1: histogram via fire-and-forget REDG (blocks 1..) | W3J (block 0)
    if (blockIdx.x == 0) {
        w3j_block(threadIdx.x);
    } else {
        const int t1   = (blockIdx.x - 1) * blockDim.x + threadIdx.x;
        const int str1 = (gridDim.x - 1) * blockDim.x;
        int ta = t1, tb = t1 + str1;
        bool ha = ta < E4, hb = tb < E4;
        int4 a, b;
        if (ha) a = ((const int4*)eto)[ta];   // both loads issued before any use
        if (hb) b = ((const int4*)eto)[tb];
        if (ha) {
            atomicAdd(&g_count[a.x], 1); atomicAdd(&g_count[a.y], 1);
            atomicAdd(&g_count[a.z], 1); atomicAdd(&g_count[a.w], 1);
        }
        if (hb) {
            atomicAdd(&g_count[b.x], 1); atomicAdd(&g_count[b.y], 1);
            atomicAdd(&g_count[b.z], 1); atomicAdd(&g_count[b.w], 1);
        }
        if (t1 < Etail) atomicAdd(&g_count[eto[E4 * 4 + t1]], 1);
    }
    gbar(0);

    // ---- P1.5: argmax over counts (packed key: max count, min index) ----
    {
        const int N4 = N >> 2;
        const int Ntail = N - N4 * 4;
        unsigned long long best = 0ull;
        for (int t = gtid; t < N4; t += stride) {
            int4 c = ((const int4*)g_count)[t];
            int i0 = 4 * t;
            best = max(best, packkey(c.x, i0));
            best = max(best, packkey(c.y, i0 + 1));
            best = max(best, packkey(c.z, i0 + 2));
            best = max(best, packkey(c.w, i0 + 3));
        }
        if (gtid < Ntail) best = max(best, packkey(g_count[N4 * 4 + gtid], N4 * 4 + gtid));
        for (int o = 16; o; o >>= 1)
            best = max(best, __shfl_down_sync(0xffffffff, best, o));
        __shared__ unsigned long long sm[8];
        int w = threadIdx.x >> 5;
        if ((threadIdx.x & 31) == 0) sm[w] = best;
        __syncthreads();
        if (threadIdx.x < 8) {
            best = sm[threadIdx.x];
            for (int o = 4; o; o >>= 1)
                best = max(best, __shfl_down_sync(0xff, best, o));
            if (threadIdx.x == 0 && best) atomicMax(&g_key, best);
        }
    }
    gbar(1);

    // ---- P2: flag Co's neighbors, zero their nodemid rows, build colist ----
    {
        int co = decode_co();
        int ta = gtid, tb = gtid + stride;
        bool ha = ta < E4, hb = tb < E4;
        int4 a, b;
        if (ha) a = ((const int4*)efrom)[ta];
        if (hb) b = ((const int4*)efrom)[tb];
        if (ha) {
            int e0 = 4 * ta;
            if (a.x == co) flag_edge(e0,     eto);
            if (a.y == co) flag_edge(e0 + 1, eto);
            if (a.z == co) flag_edge(e0 + 2, eto);
            if (a.w == co) flag_edge(e0 + 3, eto);
        }
        if (hb) {
            int e0 = 4 * tb;
            if (b.x == co) flag_edge(e0,     eto);
            if (b.y == co) flag_edge(e0 + 1, eto);
            if (b.z == co) flag_edge(e0 + 2, eto);
            if (b.w == co) flag_edge(e0 + 3, eto);
        }
        if (gtid < Etail) {
            int e = E4 * 4 + gtid;
            if (efrom[e] == co) flag_edge(e, eto);
        }
    }
    gbar(2);

    // ---- P3: scan edges; flagged sources run the MLP inline ----
    {
        int ta = gtid, tb = gtid + stride;
        bool ha = ta < E4, hb = tb < E4;
        int4 a, b;
        if (ha) a = ((const int4*)efrom)[ta];
        if (hb) b = ((const int4*)efrom)[tb];
        unsigned char fa0 = 0, fa1 = 0, fa2 = 0, fa3 = 0;
        unsigned char fb0 = 0, fb1 = 0, fb2 = 0, fb3 = 0;
        if (ha) { fa0 = g_flag[a.x]; fa1 = g_flag[a.y]; fa2 = g_flag[a.z]; fa3 = g_flag[a.w]; }
        if (hb) { fb0 = g_flag[b.x]; fb1 = g_flag[b.y]; fb2 = g_flag[b.z]; fb3 = g_flag[b.w]; }
        if (ha) {
            int e0 = 4 * ta;
            if (fa0) mid_edge(a.x, eto[e0],     x, pos, W1, W2);
            if (fa1) mid_edge(a.y, eto[e0 + 1], x, pos, W1, W2);
            if (fa2) mid_edge(a.z, eto[e0 + 2], x, pos, W1, W2);
            if (fa3) mid_edge(a.w, eto[e0 + 3], x, pos, W1, W2);
        }
        if (hb) {
            int e0 = 4 * tb;
            if (fb0) mid_edge(b.x, eto[e0],     x, pos, W1, W2);
            if (fb1) mid_edge(b.y, eto[e0 + 1], x, pos, W1, W2);
            if (fb2) mid_edge(b.z, eto[e0 + 2], x, pos, W1, W2);
            if (fb3) mid_edge(b.w, eto[e0 + 3], x, pos, W1, W2);
        }
        if (gtid < Etail) {
            int e = E4 * 4 + gtid;
            int jf = efrom[e];
            if (g_flag[jf]) mid_edge(jf, eto[e], x, pos, W1, W2);
        }
    }
    gbar(3);

    // ---- P4: final contraction over Co's edges, parallel over (edge, u) ----
    {
        int co = decode_co();
        int n = *((volatile int*)&g_cocount);
        int tot = n * 5;
        for (int w = gtid; w < tot; w += stride) {
            int i = w / 5, u = w % 5;
            int e  = g_colist[i];
            int jt = eto[e];

            float vx = pos[3 * jt + 0] - pos[3 * co + 0];
            float vy = pos[3 * jt + 1] - pos[3 * co + 1];
            float vz = pos[3 * jt + 2] - pos[3 * co + 2];
            float dist = sqrtf(vx * vx + vy * vy + vz * vz);
            float inv = 1.f / dist;
            float sh[16];
            compute_sh(vx * inv, vy * inv, vz * inv, sh);

            const float* m80 = &g_nodemid[jt * 80];
            float acc[5] = {0.f, 0.f, 0.f, 0.f, 0.f};

            for (int p = 0; p < 7; p++) {
                int l1 = c_l1[p], l2 = c_l2[p];
                int d1 = 2 * l1 + 1, d2 = 2 * l2 + 1;
                int so2 = l2 * l2, mo = c_midoff[l1], wo = c_w3off[p];
                float tw = tp2w[p * 5 + u];
                for (int ii = 0; ii < d1; ii++) {
                    float mv = m80[mo + u * d1 + ii] * tw;
                    for (int jj = 0; jj < d2; jj++) {
                        float sv = mv * sh[so2 + jj];
                        const float* W = &g_w3j[wo + (ii * d2 + jj) * 5];
                        for (int k = 0; k < 5; k++) acc[k] += W[k] * sv;
                    }
                }
            }
            const float scale = 0.3779644730092272f * 0.4082482904638631f;  // ALPHA2/sqrt(6)
            for (int k = 0; k < 5; k++) atomicAdd(&out[k], acc[k] * scale);
        }
    }
}

// ---------------------------------------------------------------------------
// Launch
// ---------------------------------------------------------------------------
extern "C" void kernel_launch(void* const* d_in, const int* in_sizes, int n_in,
                              void* d_out, int out_size) {
    const float* x     = (const float*)d_in[0];
    const float* pos   = (const float*)d_in[1];
    const int*   efrom = (const int*)d_in[2];
    const int*   eto   = (const int*)d_in[3];
    const float* W1    = (const float*)d_in[4];
    const float* W2    = (const float*)d_in[5];
    const float* tp2w  = (const float*)d_in[6];
    float* out = (float*)d_out;

    int N = in_sizes[0];
    int E = in_sizes[2];

    int initb = ((N + 3) / 4 + 255) / 256;
    k_init<<<initb, 256>>>(out, N);
    k_mega<<<MEGA_BLOCKS, 256>>>(x, pos, efrom, eto, W1, W2, tp2w, out, E, N);
}